// round 1
// baseline (speedup 1.0000x reference)
#include <cuda_runtime.h>

#define BB    8
#define NN    2000000
#define TOTAL (BB * NN)          // 16,000,000
#define NCLS  16
#define NGRP  (BB * NCLS)        // 128

#define BITMAP_WORDS (1u << 24)          // 2^24 u32 words = 2^29 bits = 64MB
#define BITIDX_MASK  ((1u << 29) - 1)
#define HLOG   21
#define HSLOTS (1u << HLOG)              // 2M slots * 8B = 16MB
#define HMASK  (HSLOTS - 1)
#define OCCBIT (1ull << 63)
#define KEYMASK ((((1ull << 39) - 1)) | OCCBIT)   // key(39b) + occupied bit
#define CNTONE  (1ull << 39)                      // count lives in bits [39,63)

// ---------------- scratch (static device globals; no allocation) ------------
__device__ __align__(16) unsigned int        g_bitmap[BITMAP_WORDS];
__device__ __align__(16) unsigned long long  g_hash[HSLOTS];
__device__ double             g_sum[NGRP];
__device__ unsigned int       g_cntg[NGRP];
__device__ unsigned int       g_minord[NGRP];
__device__ unsigned long long g_packed[NGRP];

// ---------------- helpers ----------------
__device__ __forceinline__ unsigned long long mix64(unsigned long long h) {
    h += 0x9E3779B97F4A7C15ull;
    h ^= h >> 30; h *= 0xBF58476D1CE4E5B9ull;
    h ^= h >> 27; h *= 0x94D049BB133111EBull;
    h ^= h >> 31;
    return h;
}
// order-preserving map float-bits -> u32 (smaller float => smaller uint)
__device__ __forceinline__ unsigned int orderf(unsigned int u) {
    return u ^ ((u & 0x80000000u) ? 0xFFFFFFFFu : 0x80000000u);
}

// ---------------- K1: clear scratch ----------------
__global__ void k_clear() {
    unsigned tid    = blockIdx.x * blockDim.x + threadIdx.x;
    unsigned stride = gridDim.x * blockDim.x;
    uint4 z = make_uint4(0u, 0u, 0u, 0u);
    uint4* bm = reinterpret_cast<uint4*>(g_bitmap);
    for (unsigned i = tid; i < BITMAP_WORDS / 4; i += stride) bm[i] = z;
    uint4* hh = reinterpret_cast<uint4*>(g_hash);
    for (unsigned i = tid; i < HSLOTS / 2; i += stride) hh[i] = z;
    if (tid < NGRP) {
        g_sum[tid]    = 0.0;
        g_cntg[tid]   = 0u;
        g_minord[tid] = 0xFFFFFFFFu;
        g_packed[tid] = 0ull;
    }
}

// ---------------- K2: stats + duplicate-candidate detection ----------------
#define P1_TPB    128
#define P1_CHUNK  16384
#define BLKS_PER_B ((NN + P1_CHUNK - 1) / P1_CHUNK)   // 123

__device__ __forceinline__ void insert_candidate(unsigned long long key,
                                                 unsigned long long h) {
    unsigned idx = (unsigned)(h >> 32) & HMASK;
    unsigned long long tag = key | OCCBIT;
    for (;;) {
        unsigned long long cur = __ldcg(&g_hash[idx]);
        if (cur == 0ull) {
            unsigned long long old = atomicCAS(&g_hash[idx], 0ull, tag);
            if (old == 0ull) return;
            cur = old;
        }
        if (((cur ^ tag) & KEYMASK) == 0ull) return;   // already inserted
        idx = (idx + 1) & HMASK;
    }
}

__global__ void __launch_bounds__(P1_TPB) k_pass1(const float* __restrict__ x,
                                                  const int* __restrict__ t) {
    __shared__ float        s_sum[P1_TPB * 17];
    __shared__ unsigned int s_cnt[P1_TPB * 17];
    __shared__ unsigned int s_min[P1_TPB * 17];

    const int tx = threadIdx.x;
    const int b  = blockIdx.y;
    const unsigned gbase = (unsigned)b * NCLS;

#pragma unroll
    for (int c = 0; c < 17; c++) {
        s_sum[tx * 17 + c] = 0.f;
        s_cnt[tx * 17 + c] = 0u;
        s_min[tx * 17 + c] = 0xFFFFFFFFu;
    }

    long long base = (long long)b * NN + (long long)blockIdx.x * P1_CHUNK;
    int nelem = NN - blockIdx.x * P1_CHUNK;
    if (nelem > P1_CHUNK) nelem = P1_CHUNK;
    int nv = nelem >> 2;   // NN and P1_CHUNK divisible by 4

    const float4* x4 = reinterpret_cast<const float4*>(x + base);
    const int4*   t4 = reinterpret_cast<const int4*>(t + base);

    for (int i = tx; i < nv; i += P1_TPB) {
        float4 xv = __ldcs(x4 + i);
        int4   tv = __ldcs(t4 + i);
        float vs[4] = {xv.x, xv.y, xv.z, xv.w};
        int   cs[4] = {tv.x, tv.y, tv.z, tv.w};
#pragma unroll
        for (int j = 0; j < 4; j++) {
            float v = vs[j];
            int   c = cs[j];
            int s = tx * 17 + c;
            s_sum[s] += v;
            s_cnt[s] += 1u;
            unsigned u  = __float_as_uint(v);
            unsigned ov = orderf(u);
            if (ov < s_min[s]) s_min[s] = ov;

            unsigned long long key =
                ((unsigned long long)(gbase + (unsigned)c) << 32) | u;
            unsigned long long h = mix64(key);
            unsigned bi  = (unsigned)h & BITIDX_MASK;
            unsigned bit = 1u << (bi & 31);
            unsigned old = atomicOr(&g_bitmap[bi >> 5], bit);
            if (old & bit) insert_candidate(key, h);
        }
    }
    __syncthreads();

    // block reduce per class: each thread owns its own smem column
    __shared__ float        r_sum[P1_TPB / 32][16];
    __shared__ unsigned int r_cnt[P1_TPB / 32][16];
    __shared__ unsigned int r_min[P1_TPB / 32][16];
    const int lane = tx & 31, warp = tx >> 5;
#pragma unroll
    for (int c = 0; c < 16; c++) {
        float    sv = s_sum[tx * 17 + c];
        unsigned cv = s_cnt[tx * 17 + c];
        unsigned mv = s_min[tx * 17 + c];
#pragma unroll
        for (int o = 16; o > 0; o >>= 1) {
            sv += __shfl_down_sync(0xFFFFFFFFu, sv, o);
            cv += __shfl_down_sync(0xFFFFFFFFu, cv, o);
            unsigned m2 = __shfl_down_sync(0xFFFFFFFFu, mv, o);
            mv = mv < m2 ? mv : m2;
        }
        if (lane == 0) { r_sum[warp][c] = sv; r_cnt[warp][c] = cv; r_min[warp][c] = mv; }
    }
    __syncthreads();
    if (tx < 16) {
        float    sv = 0.f; unsigned cv = 0u; unsigned mv = 0xFFFFFFFFu;
#pragma unroll
        for (int w = 0; w < P1_TPB / 32; w++) {
            sv += r_sum[w][tx];
            cv += r_cnt[w][tx];
            mv = mv < r_min[w][tx] ? mv : r_min[w][tx];
        }
        atomicAdd(&g_sum[gbase + tx], (double)sv);
        atomicAdd(&g_cntg[gbase + tx], cv);
        atomicMin(&g_minord[gbase + tx], mv);
    }
}

// ---------------- K3: exact counting of candidate keys ----------------
__device__ __forceinline__ void probe_count(unsigned grp, unsigned u) {
    unsigned long long key = ((unsigned long long)grp << 32) | u;
    unsigned long long h   = mix64(key);
    unsigned idx = (unsigned)(h >> 32) & HMASK;
    unsigned long long tag = key | OCCBIT;
    for (;;) {
        unsigned long long cur = __ldg(&g_hash[idx]);   // keys immutable here
        if (cur == 0ull) return;                        // not a candidate
        if (((cur ^ tag) & KEYMASK) == 0ull) {
            atomicAdd(&g_hash[idx], CNTONE);
            return;
        }
        idx = (idx + 1) & HMASK;
    }
}

__global__ void __launch_bounds__(256) k_pass2(const float* __restrict__ x,
                                               const int* __restrict__ t) {
    int stride = gridDim.x * blockDim.x;
    const float4* x4 = reinterpret_cast<const float4*>(x);
    const int4*   t4 = reinterpret_cast<const int4*>(t);
    for (int i = blockIdx.x * blockDim.x + threadIdx.x; i < TOTAL / 4; i += stride) {
        float4 xv = __ldcs(x4 + i);
        int4   tv = __ldcs(t4 + i);
        unsigned b  = (unsigned)((i * 4) / NN);   // NN divisible by 4: vec in one batch
        unsigned gb = b * NCLS;
        probe_count(gb + (unsigned)tv.x, __float_as_uint(xv.x));
        probe_count(gb + (unsigned)tv.y, __float_as_uint(xv.y));
        probe_count(gb + (unsigned)tv.z, __float_as_uint(xv.z));
        probe_count(gb + (unsigned)tv.w, __float_as_uint(xv.w));
    }
}

// ---------------- K4: scan hash -> per-group (maxcount, minvalue) ----------
__global__ void __launch_bounds__(256) k_scan() {
    unsigned stride = gridDim.x * blockDim.x;
    for (unsigned i = blockIdx.x * blockDim.x + threadIdx.x; i < HSLOTS; i += stride) {
        unsigned long long cur = g_hash[i];
        if (cur == 0ull) continue;
        unsigned cnt = (unsigned)((cur >> 39) & 0xFFFFFFu);
        if (cnt >= 2u) {
            unsigned grp = (unsigned)((cur >> 32) & 0x7Fu);
            unsigned u   = (unsigned)(cur & 0xFFFFFFFFull);
            unsigned ov  = orderf(u);
            unsigned long long packed =
                ((unsigned long long)cnt << 32) | (unsigned long long)(~ov);
            atomicMax(&g_packed[grp], packed);
        }
    }
}

// ---------------- K5: final scalar ----------------
__global__ void k_final(float* __restrict__ out) {
    __shared__ double red[128];
    int g = threadIdx.x;
    double contrib = 0.0;
    if (g < NGRP) {
        unsigned cnt = g_cntg[g];
        if (cnt > 0u) {
            double mean = g_sum[g] / (double)cnt;
            unsigned long long packed = g_packed[g];
            unsigned ov;
            if (packed != 0ull) {
                ov = ~((unsigned)(packed & 0xFFFFFFFFull));   // dup mode
            } else {
                ov = g_minord[g];                              // all counts == 1
            }
            unsigned u = (ov & 0x80000000u) ? (ov ^ 0x80000000u) : ~ov;
            float mode = __uint_as_float(u);
            contrib = (double)cnt * (mean - (double)mode);
        }
    }
    red[threadIdx.x] = contrib;
    __syncthreads();
    for (int s = 64; s > 0; s >>= 1) {
        if (threadIdx.x < s) red[threadIdx.x] += red[threadIdx.x + s];
        __syncthreads();
    }
    if (threadIdx.x == 0) out[0] = (float)(red[0] / (double)TOTAL);
}

// ---------------- launch ----------------
extern "C" void kernel_launch(void* const* d_in, const int* in_sizes, int n_in,
                              void* d_out, int out_size) {
    const float* x = (const float*)d_in[0];
    const int*   t = (const int*)d_in[1];
    float* out = (float*)d_out;

    k_clear<<<4096, 256>>>();
    dim3 g2(BLKS_PER_B, BB);
    k_pass1<<<g2, P1_TPB>>>(x, t);
    k_pass2<<<4096, 256>>>(x, t);
    k_scan<<<2048, 256>>>();
    k_final<<<1, 128>>>(out);
}

// round 2
// speedup vs baseline: 1.6733x; 1.6733x over previous
#include <cuda_runtime.h>

#define BB    8
#define NN    2000000
#define TOTAL (BB * NN)          // 16,000,000
#define NCLS  16
#define NGRP  (BB * NCLS)        // 128

#define BITMAP_WORDS (1u << 23)          // 2^23 u32 = 2^28 bits = 32MB
#define BITIDX_MASK  ((1u << 28) - 1)
#define HLOG   22
#define HSLOTS (1u << HLOG)              // 4M slots * 8B = 32MB
#define HMASK  (HSLOTS - 1)
#define OCCBIT (1ull << 63)
#define KEYMASK ((((1ull << 39) - 1)) | OCCBIT)   // key(39b) + occupied bit
#define CNTONE  (1ull << 39)                      // count in bits [39,63)

// ---------------- scratch (static device globals; no allocation) ------------
__device__ __align__(16) unsigned int        g_bitmap[BITMAP_WORDS];
__device__ __align__(16) unsigned long long  g_hash[HSLOTS];
__device__ double             g_sum[NGRP];
__device__ unsigned int       g_cntg[NGRP];
__device__ unsigned int       g_minord[NGRP];
__device__ unsigned long long g_packed[NGRP];

// ---------------- helpers ----------------
__device__ __forceinline__ unsigned long long mix64(unsigned long long h) {
    h += 0x9E3779B97F4A7C15ull;
    h ^= h >> 30; h *= 0xBF58476D1CE4E5B9ull;
    h ^= h >> 27; h *= 0x94D049BB133111EBull;
    h ^= h >> 31;
    return h;
}
// order-preserving map float-bits -> u32 (smaller float => smaller uint)
__device__ __forceinline__ unsigned int orderf(unsigned int u) {
    return u ^ ((u & 0x80000000u) ? 0xFFFFFFFFu : 0x80000000u);
}

// ---------------- K1: clear scratch ----------------
__global__ void k_clear() {
    unsigned tid    = blockIdx.x * blockDim.x + threadIdx.x;
    unsigned stride = gridDim.x * blockDim.x;
    uint4 z = make_uint4(0u, 0u, 0u, 0u);
    uint4* bm = reinterpret_cast<uint4*>(g_bitmap);
    for (unsigned i = tid; i < BITMAP_WORDS / 4; i += stride) bm[i] = z;
    uint4* hh = reinterpret_cast<uint4*>(g_hash);
    for (unsigned i = tid; i < HSLOTS / 2; i += stride) hh[i] = z;
    if (tid < NGRP) {
        g_sum[tid]    = 0.0;
        g_cntg[tid]   = 0u;
        g_minord[tid] = 0xFFFFFFFFu;
        g_packed[tid] = 0ull;
    }
}

// ---------------- K2: bitmap filter + candidate insert ----------------
__device__ __forceinline__ void insert_candidate(unsigned long long key) {
    unsigned long long h = mix64(key);
    unsigned idx = (unsigned)(h >> 32) & HMASK;
    unsigned long long tag = key | OCCBIT;
    for (;;) {
        unsigned long long cur = __ldcg(&g_hash[idx]);
        if (cur == 0ull) {
            unsigned long long old = atomicCAS(&g_hash[idx], 0ull, tag);
            if (old == 0ull) return;
            cur = old;
        }
        if (((cur ^ tag) & KEYMASK) == 0ull) return;   // already inserted
        idx = (idx + 1) & HMASK;
    }
}

__global__ void __launch_bounds__(256) k_filter(const float* __restrict__ x,
                                                const int* __restrict__ t) {
    const float4* x4 = reinterpret_cast<const float4*>(x);
    const int4*   t4 = reinterpret_cast<const int4*>(t);
    unsigned stride = gridDim.x * blockDim.x;
    for (unsigned i = blockIdx.x * blockDim.x + threadIdx.x; i < TOTAL / 8;
         i += stride) {
        unsigned b  = (i * 8u) / NN;       // 8-elem chunk never crosses batch
        unsigned gb = b * NCLS;
        float4 xa = __ldcs(x4 + 2 * i), xb = __ldcs(x4 + 2 * i + 1);
        int4   ta = __ldcs(t4 + 2 * i), tb = __ldcs(t4 + 2 * i + 1);
        float vs[8] = {xa.x, xa.y, xa.z, xa.w, xb.x, xb.y, xb.z, xb.w};
        int   cs[8] = {ta.x, ta.y, ta.z, ta.w, tb.x, tb.y, tb.z, tb.w};
        unsigned long long keys[8];
        unsigned words[8], bits[8], olds[8];
#pragma unroll
        for (int j = 0; j < 8; j++) {
            unsigned u = __float_as_uint(vs[j]);
            unsigned long long key =
                ((unsigned long long)(gb + (unsigned)cs[j]) << 32) | u;
            keys[j] = key;
            unsigned long long h = mix64(key);
            unsigned bi = (unsigned)h & BITIDX_MASK;
            words[j] = bi >> 5;
            bits[j]  = 1u << (bi & 31);
        }
#pragma unroll
        for (int j = 0; j < 8; j++)
            olds[j] = atomicOr(&g_bitmap[words[j]], bits[j]);
#pragma unroll
        for (int j = 0; j < 8; j++)
            if (olds[j] & bits[j]) insert_candidate(keys[j]);
    }
}

// ---------------- K3: probe/count + group stats ----------------
#define P3_TPB    128
#define P3_CHUNK  16384
#define BLKS_PER_B ((NN + P3_CHUNK - 1) / P3_CHUNK)   // 123

__device__ __forceinline__ void probe_resolve(unsigned long long key,
                                              unsigned idx,
                                              unsigned long long cur) {
    unsigned long long tag = key | OCCBIT;
    for (;;) {
        if (cur == 0ull) return;                       // not a candidate
        if (((cur ^ tag) & KEYMASK) == 0ull) {
            atomicAdd(&g_hash[idx], CNTONE);
            return;
        }
        idx = (idx + 1) & HMASK;
        cur = __ldg(&g_hash[idx]);
    }
}

__global__ void __launch_bounds__(P3_TPB) k_probe_stats(
    const float* __restrict__ x, const int* __restrict__ t) {
    // [class][thread] layout: bank = tx mod 32 -> conflict-free for any class mix
    __shared__ float        s_sum[NCLS * P3_TPB];
    __shared__ unsigned int s_cnt[NCLS * P3_TPB];
    __shared__ unsigned int s_min[NCLS * P3_TPB];

    const int tx = threadIdx.x;
    const int b  = blockIdx.y;
    const unsigned gbase = (unsigned)b * NCLS;

#pragma unroll
    for (int c = 0; c < NCLS; c++) {
        s_sum[c * P3_TPB + tx] = 0.f;
        s_cnt[c * P3_TPB + tx] = 0u;
        s_min[c * P3_TPB + tx] = 0xFFFFFFFFu;
    }
    __syncthreads();

    long long base = (long long)b * NN + (long long)blockIdx.x * P3_CHUNK;
    int nelem = NN - blockIdx.x * P3_CHUNK;
    if (nelem > P3_CHUNK) nelem = P3_CHUNK;
    int nv = nelem >> 2;

    const float4* x4 = reinterpret_cast<const float4*>(x + base);
    const int4*   t4 = reinterpret_cast<const int4*>(t + base);

    for (int i = tx; i < nv; i += P3_TPB) {
        float4 xv = __ldcs(x4 + i);
        int4   tv = __ldcs(t4 + i);
        float vs[4] = {xv.x, xv.y, xv.z, xv.w};
        int   cs[4] = {tv.x, tv.y, tv.z, tv.w};

        unsigned long long keys[4], curs[4];
        unsigned idxs[4];
#pragma unroll
        for (int j = 0; j < 4; j++) {
            unsigned u = __float_as_uint(vs[j]);
            unsigned long long key =
                ((unsigned long long)(gbase + (unsigned)cs[j]) << 32) | u;
            keys[j] = key;
            unsigned long long h = mix64(key);
            idxs[j] = (unsigned)(h >> 32) & HMASK;
        }
#pragma unroll
        for (int j = 0; j < 4; j++)
            curs[j] = __ldg(&g_hash[idxs[j]]);         // 4 probes in flight
#pragma unroll
        for (int j = 0; j < 4; j++) {
            // stats (conflict-free smem)
            int s = cs[j] * P3_TPB + tx;
            s_sum[s] += vs[j];
            s_cnt[s] += 1u;
            unsigned ov = orderf(__float_as_uint(vs[j]));
            if (ov < s_min[s]) s_min[s] = ov;
            probe_resolve(keys[j], idxs[j], curs[j]);
        }
    }
    __syncthreads();

    // block reduce per class
    __shared__ float        r_sum[P3_TPB / 32][NCLS];
    __shared__ unsigned int r_cnt[P3_TPB / 32][NCLS];
    __shared__ unsigned int r_min[P3_TPB / 32][NCLS];
    const int lane = tx & 31, warp = tx >> 5;
#pragma unroll
    for (int c = 0; c < NCLS; c++) {
        float    sv = s_sum[c * P3_TPB + tx];
        unsigned cv = s_cnt[c * P3_TPB + tx];
        unsigned mv = s_min[c * P3_TPB + tx];
#pragma unroll
        for (int o = 16; o > 0; o >>= 1) {
            sv += __shfl_down_sync(0xFFFFFFFFu, sv, o);
            cv += __shfl_down_sync(0xFFFFFFFFu, cv, o);
            unsigned m2 = __shfl_down_sync(0xFFFFFFFFu, mv, o);
            mv = mv < m2 ? mv : m2;
        }
        if (lane == 0) { r_sum[warp][c] = sv; r_cnt[warp][c] = cv; r_min[warp][c] = mv; }
    }
    __syncthreads();
    if (tx < NCLS) {
        float    sv = 0.f; unsigned cv = 0u; unsigned mv = 0xFFFFFFFFu;
#pragma unroll
        for (int w = 0; w < P3_TPB / 32; w++) {
            sv += r_sum[w][tx];
            cv += r_cnt[w][tx];
            mv = mv < r_min[w][tx] ? mv : r_min[w][tx];
        }
        atomicAdd(&g_sum[gbase + tx], (double)sv);
        atomicAdd(&g_cntg[gbase + tx], cv);
        atomicMin(&g_minord[gbase + tx], mv);
    }
}

// ---------------- K4: scan hash -> per-group (maxcount, minvalue) ----------
__global__ void __launch_bounds__(256) k_scan() {
    const uint4* h4 = reinterpret_cast<const uint4*>(g_hash);
    unsigned stride = gridDim.x * blockDim.x;
    for (unsigned i = blockIdx.x * blockDim.x + threadIdx.x; i < HSLOTS / 2;
         i += stride) {
        uint4 w = __ldcs(h4 + i);
        unsigned long long s0 = ((unsigned long long)w.y << 32) | w.x;
        unsigned long long s1 = ((unsigned long long)w.w << 32) | w.z;
#pragma unroll
        for (int k = 0; k < 2; k++) {
            unsigned long long cur = k ? s1 : s0;
            unsigned cnt = (unsigned)((cur >> 39) & 0xFFFFFFu);
            if (cnt >= 2u) {
                unsigned grp = (unsigned)((cur >> 32) & 0x7Fu);
                unsigned u   = (unsigned)(cur & 0xFFFFFFFFull);
                unsigned ov  = orderf(u);
                unsigned long long packed =
                    ((unsigned long long)cnt << 32) |
                    (unsigned long long)(~ov);
                atomicMax(&g_packed[grp], packed);
            }
        }
    }
}

// ---------------- K5: final scalar ----------------
__global__ void k_final(float* __restrict__ out) {
    __shared__ double red[128];
    int g = threadIdx.x;
    double contrib = 0.0;
    if (g < NGRP) {
        unsigned cnt = g_cntg[g];
        if (cnt > 0u) {
            double mean = g_sum[g] / (double)cnt;
            unsigned long long packed = g_packed[g];
            unsigned ov;
            if (packed != 0ull) {
                ov = ~((unsigned)(packed & 0xFFFFFFFFull));   // dup mode
            } else {
                ov = g_minord[g];                              // all counts == 1
            }
            unsigned u = (ov & 0x80000000u) ? (ov ^ 0x80000000u) : ~ov;
            float mode = __uint_as_float(u);
            contrib = (double)cnt * (mean - (double)mode);
        }
    }
    red[threadIdx.x] = contrib;
    __syncthreads();
    for (int s = 64; s > 0; s >>= 1) {
        if (threadIdx.x < s) red[threadIdx.x] += red[threadIdx.x + s];
        __syncthreads();
    }
    if (threadIdx.x == 0) out[0] = (float)(red[0] / (double)TOTAL);
}

// ---------------- launch ----------------
extern "C" void kernel_launch(void* const* d_in, const int* in_sizes, int n_in,
                              void* d_out, int out_size) {
    const float* x = (const float*)d_in[0];
    const int*   t = (const int*)d_in[1];
    float* out = (float*)d_out;

    k_clear<<<4096, 256>>>();
    k_filter<<<4096, 256>>>(x, t);
    dim3 g3(BLKS_PER_B, BB);
    k_probe_stats<<<g3, P3_TPB>>>(x, t);
    k_scan<<<1024, 256>>>();
    k_final<<<1, 128>>>(out);
}